// round 7
// baseline (speedup 1.0000x reference)
#include <cuda_runtime.h>
#include <cstdint>
#include <cstddef>

// ---------------- problem constants ----------------
#define NCAV     2
#define WIN      8
#define BWIN     2048
#define NTOK     64
#define CH       256
#define NHEAD    8
#define HD       32
#define MROWS    (BWIN*NTOK)    // 131072
#define SCALE_Q  0.17677669529663687f
#define PI_F     3.14159274101257324f

// ---------------- scratch ----------------
__device__ float g_q [BWIN*NHEAD*NTOK*HD];
__device__ float g_k [BWIN*NHEAD*NTOK*HD];
__device__ float g_v [BWIN*NHEAD*NTOK*HD];
__device__ float g_ao[(size_t)MROWS*CH];     // attn output (rounded)
__device__ float g_wqkv[768*CH];             // [n][k] transposed, tf32-rounded
__device__ float g_wp[CH*CH];                // [n][k] transposed, tf32-rounded
__device__ float g_bqkv[768];
__device__ int   g_egoidx[BWIN];

// ---------------- helpers ----------------
__device__ __forceinline__ float rndtf(float f) {
    uint32_t r;
    asm("cvt.rna.tf32.f32 %0, %1;\n" : "=r"(r) : "f"(f));
    return __uint_as_float(r);
}

__device__ __forceinline__ uint32_t rndtf_u(uint32_t u) {
    uint32_t r;
    asm("cvt.rna.tf32.f32 %0, %1;\n" : "=r"(r) : "r"(u));
    return r;
}

__device__ __forceinline__ void mma_tf32(float c[4], const uint32_t a[4], const uint32_t b[2]) {
    asm volatile(
        "mma.sync.aligned.m16n8k8.row.col.f32.tf32.tf32.f32 "
        "{%0,%1,%2,%3},{%4,%5,%6,%7},{%8,%9},{%0,%1,%2,%3};\n"
        : "+f"(c[0]), "+f"(c[1]), "+f"(c[2]), "+f"(c[3])
        : "r"(a[0]), "r"(a[1]), "r"(a[2]), "r"(a[3]), "r"(b[0]), "r"(b[1]));
}

__device__ __forceinline__ void ldsm4(uint32_t& r0, uint32_t& r1, uint32_t& r2, uint32_t& r3,
                                      uint32_t saddr) {
    asm volatile("ldmatrix.sync.aligned.m8n8.x4.shared.b16 {%0,%1,%2,%3}, [%4];\n"
                 : "=r"(r0), "=r"(r1), "=r"(r2), "=r"(r3) : "r"(saddr));
}

__device__ __forceinline__ void cpasync16(void* s, const void* g) {
    uint32_t sa = (uint32_t)__cvta_generic_to_shared(s);
    asm volatile("cp.async.cg.shared.global [%0], [%1], 16;\n" :: "r"(sa), "l"(g));
}

// ---------------- kernel 1: pack weights transposed [n][k], tf32-rounded ----
__global__ void pack_kernel(const float* __restrict__ Wq, const float* __restrict__ bq,
                            const float* __restrict__ Wkv, const float* __restrict__ bkv,
                            const float* __restrict__ Wp) {
    int t = blockIdx.x * blockDim.x + threadIdx.x;  // 196608
    int n = t >> 8, k = t & 255;
    g_wqkv[t] = rndtf((n < CH) ? Wq[k*CH + n] : Wkv[k*512 + (n - CH)]);
    if (t < 768) g_bqkv[t] = (t < CH) ? bq[t] : bkv[t - CH];
    if (t < CH*CH) g_wp[t] = rndtf(Wp[k*CH + n]);
}

// ---------------- kernel 2: ego bias bin index ----------------
__global__ void ego_kernel(const float* __restrict__ A) {
    __shared__ float rx[BWIN], ry[BWIN];
    __shared__ float red[256];
    int tid = threadIdx.x;
    float ex[NCAV], ey[NCAV];
#pragma unroll
    for (int c = 0; c < NCAV; c++) {
        ex[c] = A[c*6 + 0] * 128.0f + A[c*6 + 1] * 128.0f + A[c*6 + 2];
        ey[c] = A[c*6 + 3] * 128.0f + A[c*6 + 4] * 128.0f + A[c*6 + 5];
    }
    float lmax = 0.0f;
    for (int i = tid; i < BWIN; i += 256) {
        int cav = i >> 10, wi = i & 1023;
        int gy = wi >> 5, gx = wi & 31;
        float cx = gx * (float)WIN + WIN * 0.5f;
        float cy = gy * (float)WIN + WIN * 0.5f;
        float rxx = cx - ex[cav], ryy = cy - ey[cav];
        rx[i] = rxx; ry[i] = ryy;
        lmax = fmaxf(lmax, sqrtf(rxx*rxx + ryy*ryy));
    }
    red[tid] = lmax;
    __syncthreads();
    for (int s = 128; s > 0; s >>= 1) {
        if (tid < s) red[tid] = fmaxf(red[tid], red[tid + s]);
        __syncthreads();
    }
    float maxd = red[0] + 1e-6f;
    for (int i = tid; i < BWIN; i += 256) {
        float rxx = rx[i], ryy = ry[i];
        float d = sqrtf(rxx*rxx + ryy*ryy);
        int db = (int)(d / maxd * 3.0f);
        float ang = atan2f(ryy, rxx);
        int ab = (int)((ang + PI_F) / (2.0f * PI_F) * 3.0f);
        g_egoidx[i] = db * 4 + ab;
    }
}

// ---------------- GEMM: kTile=32, 2-stage cp.async, 1 barrier/iter ----------
// C[M,N] = A[M,256] @ B^T + bias, B stored [n][k].
// smem: As[2][128][36] then Bs[2][128][36]  (73728 B) -> 2 CTAs/SM
#define AS_IDX(st, r, c) (((st)*128 + (r))*36 + (c))
#define BS_IDX(st, r, c) (9216 + ((st)*128 + (r))*36 + (c))

#define GEMM_ISSUE(st, kt) do {                                               \
    _Pragma("unroll")                                                         \
    for (int ii = 0; ii < 8; ii++) {                                          \
        int c = tid + ii * 256;                                               \
        if (c < 1024) { int row = c >> 3, kk = (c & 7) * 4;                   \
            cpasync16(&smem[AS_IDX(st, row, kk)],                             \
                      Ap + (size_t)(bm0 + row) * 256 + (kt) * 32 + kk); }     \
        else { int c2 = c - 1024; int row = c2 >> 3, kk = (c2 & 7) * 4;       \
            cpasync16(&smem[BS_IDX(st, row, kk)],                             \
                      Bp + (size_t)(bn0 + row) * 256 + (kt) * 32 + kk); }     \
    }                                                                         \
    asm volatile("cp.async.commit_group;\n");                                 \
} while (0)

#define LOAD_FRAGS(buf, st, ks) do {                                          \
    _Pragma("unroll")                                                         \
    for (int mt = 0; mt < 4; mt++)                                            \
        ldsm4(af[buf][mt][0], af[buf][mt][1], af[buf][mt][2], af[buf][mt][3], \
              smemBase + AS_IDX(st, wm + mt*16 + aRow, (ks) + aCol) * 4);     \
    _Pragma("unroll")                                                         \
    for (int p = 0; p < 2; p++)                                               \
        ldsm4(bf[buf][2*p][0], bf[buf][2*p][1], bf[buf][2*p+1][0], bf[buf][2*p+1][1], \
              smemBase + BS_IDX(st, wn + p*16 + bRow, (ks) + bCol) * 4);      \
    _Pragma("unroll")                                                         \
    for (int mt = 0; mt < 4; mt++) {                                          \
        af[buf][mt][0] = rndtf_u(af[buf][mt][0]);                             \
        af[buf][mt][1] = rndtf_u(af[buf][mt][1]);                             \
        af[buf][mt][2] = rndtf_u(af[buf][mt][2]);                             \
        af[buf][mt][3] = rndtf_u(af[buf][mt][3]);                             \
    }                                                                         \
} while (0)

__global__ __launch_bounds__(256, 2) void gemm_tf32(
    const float* __restrict__ A_in, const float* __restrict__ bias_ext,
    int mode, float* __restrict__ out)
{
    extern __shared__ float smem[];
    const float* __restrict__ Ap    = (mode == 0) ? A_in : g_ao;
    const float* __restrict__ Bp    = (mode == 0) ? g_wqkv : g_wp;
    const float* __restrict__ biasp = (mode == 0) ? g_bqkv : bias_ext;

    const int bm0 = blockIdx.y * 128;
    const int bn0 = blockIdx.x * 128;
    int tid = threadIdx.x, warp = tid >> 5, lane = tid & 31;
    int wm = (warp & 1) * 64, wn = (warp >> 1) * 32;
    int gid = lane >> 2, tig = lane & 3;

    uint32_t smemBase = (uint32_t)__cvta_generic_to_shared(smem);
    int aRow = lane & 15;
    int aCol = (lane >> 4) << 2;
    int bRow = ((lane >> 4) << 3) + (lane & 7);
    int bCol = ((lane >> 3) & 1) << 2;

    float acc[4][4][4];
#pragma unroll
    for (int i = 0; i < 4; i++)
#pragma unroll
        for (int j = 0; j < 4; j++)
#pragma unroll
            for (int e = 0; e < 4; e++) acc[i][j][e] = 0.0f;

    GEMM_ISSUE(0, 0);

#pragma unroll
    for (int kt = 0; kt < 8; kt++) {
        int st = kt & 1;
        asm volatile("cp.async.wait_group 0;\n");   // stage kt arrived
        __syncthreads();                            // visibility + frees other buffer
        if (kt + 1 < 8) GEMM_ISSUE(st ^ 1, kt + 1); // overlaps compute below

        uint32_t af[2][4][4], bf[2][4][2];
        LOAD_FRAGS(0, st, 0);
#pragma unroll
        for (int ksq = 0; ksq < 4; ksq++) {
            int cur = ksq & 1;
            if (ksq < 3) LOAD_FRAGS(cur ^ 1, st, (ksq + 1) * 8);
#pragma unroll
            for (int mt = 0; mt < 4; mt++)
#pragma unroll
                for (int nt = 0; nt < 4; nt++)
                    mma_tf32(acc[mt][nt], af[cur][mt], bf[cur][nt]);
        }
    }

    // epilogue
#pragma unroll
    for (int mt = 0; mt < 4; mt++) {
#pragma unroll
        for (int nt = 0; nt < 4; nt++) {
            int n = bn0 + wn + nt * 8 + 2 * tig;
            float b0 = biasp[n], b1 = biasp[n + 1];
#pragma unroll
            for (int half = 0; half < 2; half++) {
                int m = bm0 + wm + mt * 16 + gid + half * 8;
                float v0 = acc[mt][nt][half * 2]     + b0;
                float v1 = acc[mt][nt][half * 2 + 1] + b1;
                if (mode == 0) {
                    int part = n >> 8, cc = n & 255;
                    int head = cc >> 5, d = cc & 31;
                    int b = m >> 6, tok = m & 63;
                    if (part == 0) { v0 *= SCALE_Q; v1 *= SCALE_Q; }
                    float* dst = (part == 0) ? g_q : ((part == 1) ? g_k : g_v);
                    float2 r2; r2.x = rndtf(v0); r2.y = rndtf(v1);
                    *(float2*)&dst[(((size_t)(b * NHEAD + head)) * NTOK + tok) * HD + d] = r2;
                } else {
                    float2 r2; r2.x = v0; r2.y = v1;
                    *(float2*)&out[(size_t)m * CH + n] = r2;
                }
            }
        }
    }
}

// ---------------- tensor-core attention (sP overlays sq/sk) ----------------
__global__ __launch_bounds__(128) void attn_kernel(
    const float* __restrict__ rel_table, const float* __restrict__ ego_table,
    const float* __restrict__ wvec)
{
    __shared__ float sQK[2 * NTOK * 36];   // sq then sk; sP (64x68=4352) overlays (4608)
    __shared__ float svT[HD][68];          // V^T [d][m]
    __shared__ float srel[225];

    float* sq = sQK;
    float* sk = sQK + NTOK * 36;

    int bh = blockIdx.x;
    int b = bh >> 3, head = bh & 7;
    int tid = threadIdx.x, warp = tid >> 5, lane = tid & 31;
    int gid = lane >> 2, tig = lane & 3;
    int wm = warp * 16;
    size_t base = (size_t)bh * (NTOK * HD);

    int n0 = wm + gid, n1 = wm + gid + 8;

    uint32_t sqB  = (uint32_t)__cvta_generic_to_shared(sq);
    uint32_t skB  = (uint32_t)__cvta_generic_to_shared(sk);
    uint32_t svTB = (uint32_t)__cvta_generic_to_shared(&svT[0][0]);
    uint32_t sPB  = sqB;   // overlay

    int aRow = lane & 15;
    int aCol = (lane >> 4) << 2;
    int bRow = ((lane >> 4) << 3) + (lane & 7);
    int bCol = ((lane >> 3) & 1) << 2;

    // tiles (q/k/v already tf32-rounded by GEMM epilogue)
#pragma unroll
    for (int i = 0; i < 4; i++) {
        int v = tid + i * 128;
        int row = v >> 3, c4 = v & 7;
        *(float4*)&sq[row * 36 + c4 * 4] = *(const float4*)(g_q + base + row * HD + c4 * 4);
        *(float4*)&sk[row * 36 + c4 * 4] = *(const float4*)(g_k + base + row * HD + c4 * 4);
        float4 vd = *(const float4*)(g_v + base + row * HD + c4 * 4);
        svT[c4*4 + 0][row] = vd.x;
        svT[c4*4 + 1][row] = vd.y;
        svT[c4*4 + 2][row] = vd.z;
        svT[c4*4 + 3][row] = vd.w;
    }
    for (int i = tid; i < 225; i += 128) srel[i] = rel_table[i * NHEAD + head];
    __syncthreads();

    // ---- S = q @ k^T ----
    float sacc[8][4];
#pragma unroll
    for (int nt = 0; nt < 8; nt++)
#pragma unroll
        for (int e = 0; e < 4; e++) sacc[nt][e] = 0.0f;

#pragma unroll
    for (int ksi = 0; ksi < 4; ksi++) {
        uint32_t qf[4], bf[8][2];
        ldsm4(qf[0], qf[1], qf[2], qf[3],
              sqB + ((wm + aRow) * 36 + ksi*8 + aCol) * 4);
#pragma unroll
        for (int p = 0; p < 4; p++)
            ldsm4(bf[2*p][0], bf[2*p][1], bf[2*p+1][0], bf[2*p+1][1],
                  skB + ((p*16 + bRow) * 36 + ksi*8 + bCol) * 4);
#pragma unroll
        for (int nt = 0; nt < 8; nt++) mma_tf32(sacc[nt], qf, bf[nt]);
    }

    // biases
    float ego_b = ego_table[g_egoidx[b] * NHEAD + head];
    int ny0 = n0 >> 3, nx0 = n0 & 7, ny1 = n1 >> 3, nx1 = n1 & 7;
#pragma unroll
    for (int nt = 0; nt < 8; nt++) {
#pragma unroll
        for (int e = 0; e < 4; e++) {
            int m = nt * 8 + 2 * tig + (e & 1);
            int my = m >> 3, mx = m & 7;
            int ny = (e < 2) ? ny0 : ny1, nx = (e < 2) ? nx0 : nx1;
            sacc[nt][e] += srel[(ny - my + 7) * 15 + (nx - mx + 7)] + ego_b;
        }
    }

    // mixing weights
    float w0 = wvec[0], w1 = wvec[1];
    float mw = fmaxf(w0, w1);
    float e0w = __expf(w0 - mw), e1w = __expf(w1 - mw);
    float inv_w = 1.0f / (e0w + e1w);
    float ws0 = e0w * inv_w, ws1 = e1w * inv_w;

    // ---- register softmax over quad ----
    float mx0 = -1e30f, mx1 = -1e30f;
#pragma unroll
    for (int nt = 0; nt < 8; nt++) {
        mx0 = fmaxf(mx0, fmaxf(sacc[nt][0], sacc[nt][1]));
        mx1 = fmaxf(mx1, fmaxf(sacc[nt][2], sacc[nt][3]));
    }
    mx0 = fmaxf(mx0, __shfl_xor_sync(0xffffffffu, mx0, 1));
    mx0 = fmaxf(mx0, __shfl_xor_sync(0xffffffffu, mx0, 2));
    mx1 = fmaxf(mx1, __shfl_xor_sync(0xffffffffu, mx1, 1));
    mx1 = fmaxf(mx1, __shfl_xor_sync(0xffffffffu, mx1, 2));

    float sum0 = 0.0f, sum1 = 0.0f;
#pragma unroll
    for (int nt = 0; nt < 8; nt++) {
        sum0 += __expf(sacc[nt][0] - mx0);
        sum0 += __expf(sacc[nt][1] - mx0);
        sum1 += __expf(sacc[nt][2] - mx1);
        sum1 += __expf(sacc[nt][3] - mx1);
    }
    sum0 += __shfl_xor_sync(0xffffffffu, sum0, 1);
    sum0 += __shfl_xor_sync(0xffffffffu, sum0, 2);
    sum1 += __shfl_xor_sync(0xffffffffu, sum1, 1);
    sum1 += __shfl_xor_sync(0xffffffffu, sum1, 2);
    float inv0 = 1.0f / sum0, inv1 = 1.0f / sum1;

    __syncthreads();   // all warps done reading sq/sk -> safe to overlay sP

#pragma unroll
    for (int nt = 0; nt < 8; nt++) {
        float r0a = fmaxf(sacc[nt][0], 0.0f), r0b = fmaxf(sacc[nt][1], 0.0f);
        float r1a = fmaxf(sacc[nt][2], 0.0f), r1b = fmaxf(sacc[nt][3], 0.0f);
        float2 P0, P1;
        P0.x = rndtf(ws0 * __expf(sacc[nt][0] - mx0) * inv0 + ws1 * r0a * r0a);
        P0.y = rndtf(ws0 * __expf(sacc[nt][1] - mx0) * inv0 + ws1 * r0b * r0b);
        P1.x = rndtf(ws0 * __expf(sacc[nt][2] - mx1) * inv1 + ws1 * r1a * r1a);
        P1.y = rndtf(ws0 * __expf(sacc[nt][3] - mx1) * inv1 + ws1 * r1b * r1b);
        *(float2*)&sQK[n0 * 68 + nt * 8 + 2 * tig] = P0;
        *(float2*)&sQK[n1 * 68 + nt * 8 + 2 * tig] = P1;
    }
    __syncwarp();      // each warp only reads its own sP rows below

    // ---- O = P @ V ----
    float oacc[4][4];
#pragma unroll
    for (int nt = 0; nt < 4; nt++)
#pragma unroll
        for (int e = 0; e < 4; e++) oacc[nt][e] = 0.0f;

#pragma unroll
    for (int ksi = 0; ksi < 8; ksi++) {
        uint32_t pf[4], vf[4][2];
        ldsm4(pf[0], pf[1], pf[2], pf[3],
              sPB + ((wm + aRow) * 68 + ksi*8 + aCol) * 4);
#pragma unroll
        for (int pp = 0; pp < 2; pp++)
            ldsm4(vf[2*pp][0], vf[2*pp][1], vf[2*pp+1][0], vf[2*pp+1][1],
                  svTB + ((pp*16 + bRow) * 68 + ksi*8 + bCol) * 4);
#pragma unroll
        for (int nt = 0; nt < 4; nt++) mma_tf32(oacc[nt], pf, vf[nt]);
    }

    // store rounded: feeds the mode-1 GEMM
    float* aop = g_ao + (size_t)(b * NTOK) * CH + head * HD;
#pragma unroll
    for (int nt = 0; nt < 4; nt++) {
        int d0 = nt * 8 + 2 * tig;
        float2 s0, s1;
        s0.x = rndtf(oacc[nt][0]); s0.y = rndtf(oacc[nt][1]);
        s1.x = rndtf(oacc[nt][2]); s1.y = rndtf(oacc[nt][3]);
        *(float2*)(aop + (size_t)n0 * CH + d0) = s0;
        *(float2*)(aop + (size_t)n1 * CH + d0) = s1;
    }
}

// ---------------- launch ----------------
extern "C" void kernel_launch(void* const* d_in, const int* in_sizes, int n_in,
                              void* d_out, int out_size) {
    const float* x    = (const float*)d_in[0];
    const float* aff  = (const float*)d_in[1];
    const float* Wq   = (const float*)d_in[2];
    const float* bq   = (const float*)d_in[3];
    const float* Wkv  = (const float*)d_in[4];
    const float* bkv  = (const float*)d_in[5];
    const float* Wp   = (const float*)d_in[6];
    const float* bp   = (const float*)d_in[7];
    const float* rel  = (const float*)d_in[8];
    const float* ego  = (const float*)d_in[9];
    const float* w    = (const float*)d_in[10];
    float* out = (float*)d_out;

    const int GEMM_SMEM = 2 * 2 * 128 * 36 * 4;   // 73728 B -> 2 CTAs/SM
    static int attr_set = 0;
    if (!attr_set) {
        cudaFuncSetAttribute(gemm_tf32, cudaFuncAttributeMaxDynamicSharedMemorySize, GEMM_SMEM);
        attr_set = 1;
    }

    pack_kernel<<<768, 256>>>(Wq, bq, Wkv, bkv, Wp);
    ego_kernel<<<1, 256>>>(aff);
    gemm_tf32<<<dim3(6, 1024), 256, GEMM_SMEM>>>(x, nullptr, 0, nullptr);
    attn_kernel<<<BWIN * NHEAD, 128>>>(rel, ego, w);
    gemm_tf32<<<dim3(2, 1024), 256, GEMM_SMEM>>>(nullptr, bp, 1, out);
}

// round 9
// speedup vs baseline: 1.4814x; 1.4814x over previous
#include <cuda_runtime.h>
#include <cuda_fp16.h>
#include <cstdint>
#include <cstddef>

// ---------------- problem constants ----------------
#define NCAV     2
#define WIN      8
#define BWIN     2048
#define NTOK     64
#define CH       256
#define NHEAD    8
#define HD       32
#define MROWS    (BWIN*NTOK)    // 131072
#define SCALE_Q  0.17677669529663687f
#define PI_F     3.14159274101257324f

// ---------------- scratch (fp16 pipeline) ----------------
__device__ __half g_xh  [(size_t)MROWS*CH];       // x, fp16
__device__ __half g_qh  [BWIN*NHEAD*NTOK*HD];
__device__ __half g_kh  [BWIN*NHEAD*NTOK*HD];
__device__ __half g_vh  [BWIN*NHEAD*NTOK*HD];
__device__ __half g_aoh [(size_t)MROWS*CH];       // attn output, fp16
__device__ __half g_wqkvh[768*CH];                // [n][k] transposed fp16
__device__ __half g_wph [CH*CH];                  // [n][k] transposed fp16
__device__ float  g_bqkv[768];
__device__ int    g_egoidx[BWIN];

// ---------------- helpers ----------------
__device__ __forceinline__ void mma_f16(float c[4], const uint32_t a[4], const uint32_t b[2]) {
    asm volatile(
        "mma.sync.aligned.m16n8k16.row.col.f32.f16.f16.f32 "
        "{%0,%1,%2,%3},{%4,%5,%6,%7},{%8,%9},{%0,%1,%2,%3};\n"
        : "+f"(c[0]), "+f"(c[1]), "+f"(c[2]), "+f"(c[3])
        : "r"(a[0]), "r"(a[1]), "r"(a[2]), "r"(a[3]), "r"(b[0]), "r"(b[1]));
}

__device__ __forceinline__ void ldsm4(uint32_t& r0, uint32_t& r1, uint32_t& r2, uint32_t& r3,
                                      uint32_t saddr) {
    asm volatile("ldmatrix.sync.aligned.m8n8.x4.shared.b16 {%0,%1,%2,%3}, [%4];\n"
                 : "=r"(r0), "=r"(r1), "=r"(r2), "=r"(r3) : "r"(saddr));
}

__device__ __forceinline__ void cpasync16(void* s, const void* g) {
    uint32_t sa = (uint32_t)__cvta_generic_to_shared(s);
    asm volatile("cp.async.cg.shared.global [%0], [%1], 16;\n" :: "r"(sa), "l"(g));
}

// ---------------- kernel 1: pack weights transposed [n][k] fp16 ----------------
__global__ void pack_kernel(const float* __restrict__ Wq, const float* __restrict__ bq,
                            const float* __restrict__ Wkv, const float* __restrict__ bkv,
                            const float* __restrict__ Wp) {
    int t = blockIdx.x * blockDim.x + threadIdx.x;  // 196608
    int n = t >> 8, k = t & 255;
    g_wqkvh[t] = __float2half_rn((n < CH) ? Wq[k*CH + n] : Wkv[k*512 + (n - CH)]);
    if (t < 768) g_bqkv[t] = (t < CH) ? bq[t] : bkv[t - CH];
    if (t < CH*CH) g_wph[t] = __float2half_rn(Wp[k*CH + n]);
}

// ---------------- kernel 2: x -> fp16 ----------------
__global__ void prep_x(const float* __restrict__ x) {
    size_t i = ((size_t)blockIdx.x * 256 + threadIdx.x) * 8;
    float4 a = *(const float4*)(x + i);
    float4 b = *(const float4*)(x + i + 4);
    __half2 h[4];
    h[0] = __floats2half2_rn(a.x, a.y);
    h[1] = __floats2half2_rn(a.z, a.w);
    h[2] = __floats2half2_rn(b.x, b.y);
    h[3] = __floats2half2_rn(b.z, b.w);
    *(uint4*)(g_xh + i) = *(uint4*)h;
}

// ---------------- kernel 3: ego bias bin index ----------------
__global__ void ego_kernel(const float* __restrict__ A) {
    __shared__ float rx[BWIN], ry[BWIN];
    __shared__ float red[256];
    int tid = threadIdx.x;
    float ex[NCAV], ey[NCAV];
#pragma unroll
    for (int c = 0; c < NCAV; c++) {
        ex[c] = A[c*6 + 0] * 128.0f + A[c*6 + 1] * 128.0f + A[c*6 + 2];
        ey[c] = A[c*6 + 3] * 128.0f + A[c*6 + 4] * 128.0f + A[c*6 + 5];
    }
    float lmax = 0.0f;
    for (int i = tid; i < BWIN; i += 256) {
        int cav = i >> 10, wi = i & 1023;
        int gy = wi >> 5, gx = wi & 31;
        float cx = gx * (float)WIN + WIN * 0.5f;
        float cy = gy * (float)WIN + WIN * 0.5f;
        float rxx = cx - ex[cav], ryy = cy - ey[cav];
        rx[i] = rxx; ry[i] = ryy;
        lmax = fmaxf(lmax, sqrtf(rxx*rxx + ryy*ryy));
    }
    red[tid] = lmax;
    __syncthreads();
    for (int s = 128; s > 0; s >>= 1) {
        if (tid < s) red[tid] = fmaxf(red[tid], red[tid + s]);
        __syncthreads();
    }
    float maxd = red[0] + 1e-6f;
    for (int i = tid; i < BWIN; i += 256) {
        float rxx = rx[i], ryy = ry[i];
        float d = sqrtf(rxx*rxx + ryy*ryy);
        int db = (int)(d / maxd * 3.0f);
        float ang = atan2f(ryy, rxx);
        int ab = (int)((ang + PI_F) / (2.0f * PI_F) * 3.0f);
        g_egoidx[i] = db * 4 + ab;
    }
}

// ---------------- GEMM fp16: resident B-tile + streamed A k-tiles ----------
// C[M,N] = A[M,256] @ B^T + bias, B [n][k] fp16.
// dyn smem (halfs): Bs[128][264] then As[2][128][40]   (88064 B)
#define BS_OFF(r, c)      ((r)*264 + (c))
#define AS_OFF(st, r, c)  (33792 + ((st)*128 + (r))*40 + (c))

#define ISSUE_A(st, kt) do {                                                  \
    _Pragma("unroll")                                                         \
    for (int ii = 0; ii < 2; ii++) {                                          \
        int c = tid + ii * 256;                                               \
        int row = c >> 2, kc = (c & 3) * 8;                                   \
        cpasync16(&hsm[AS_OFF(st, row, kc)],                                  \
                  Ap + (size_t)(bm0 + row) * 256 + (kt) * 32 + kc);           \
    }                                                                         \
    asm volatile("cp.async.commit_group;\n");                                 \
} while (0)

#define LOAD_FRAGS(buf, st, kglob, ks) do {                                   \
    _Pragma("unroll")                                                         \
    for (int mt = 0; mt < 4; mt++)                                            \
        ldsm4(af[buf][mt][0], af[buf][mt][1], af[buf][mt][2], af[buf][mt][3], \
              smemBase + AS_OFF(st, wm + mt*16 + aRow, (ks) + aCol) * 2);     \
    _Pragma("unroll")                                                         \
    for (int p = 0; p < 2; p++)                                               \
        ldsm4(bf[buf][2*p][0], bf[buf][2*p][1], bf[buf][2*p+1][0], bf[buf][2*p+1][1], \
              smemBase + BS_OFF(wn + p*16 + bRow, (kglob) + (ks) + bCol) * 2);\
} while (0)

__global__ __launch_bounds__(256, 2) void gemm_f16(
    const float* __restrict__ bias_ext, int mode, float* __restrict__ out)
{
    extern __shared__ __half hsm[];
    const __half* __restrict__ Ap    = (mode == 0) ? g_xh : g_aoh;
    const __half* __restrict__ Bp    = (mode == 0) ? g_wqkvh : g_wph;
    const float*  __restrict__ biasp = (mode == 0) ? g_bqkv : bias_ext;

    const int bm0 = blockIdx.y * 128;
    const int bn0 = blockIdx.x * 128;
    int tid = threadIdx.x, warp = tid >> 5, lane = tid & 31;
    int wm = (warp & 1) * 64, wn = (warp >> 1) * 32;
    int gid = lane >> 2, tig = lane & 3;

    uint32_t smemBase = (uint32_t)__cvta_generic_to_shared(hsm);
    int aRow = lane & 15;                         // A row within 16-tile
    int aCol = (lane >> 4) * 8;                   // A k-halfword group
    int bRow = ((lane >> 4) << 3) + (lane & 7);   // B n row
    int bCol = ((lane >> 3) & 1) * 8;             // B k-halfword group

    // prologue: resident B tile 128x256 halfs (16 cp/thread), then A stage 0
#pragma unroll
    for (int ii = 0; ii < 16; ii++) {
        int c = tid + ii * 256;
        int row = c >> 5, kc = (c & 31) * 8;
        cpasync16(&hsm[BS_OFF(row, kc)], Bp + (size_t)(bn0 + row) * 256 + kc);
    }
    asm volatile("cp.async.commit_group;\n");
    ISSUE_A(0, 0);

    float acc[4][4][4];
#pragma unroll
    for (int i = 0; i < 4; i++)
#pragma unroll
        for (int j = 0; j < 4; j++)
#pragma unroll
            for (int e = 0; e < 4; e++) acc[i][j][e] = 0.0f;

#pragma unroll
    for (int kt = 0; kt < 8; kt++) {
        int st = kt & 1;
        asm volatile("cp.async.wait_group 0;\n");
        __syncthreads();
        if (kt + 1 < 8) ISSUE_A(st ^ 1, kt + 1);  // overlaps compute below

        uint32_t af[2][4][4], bf[2][4][2];
        LOAD_FRAGS(0, st, kt * 32, 0);
#pragma unroll
        for (int ksq = 0; ksq < 2; ksq++) {       // two k16 steps per 32-k tile
            int cur = ksq & 1;
            if (ksq == 0) LOAD_FRAGS(1, st, kt * 32, 16);
#pragma unroll
            for (int mt = 0; mt < 4; mt++)
#pragma unroll
                for (int nt = 0; nt < 4; nt++)
                    mma_f16(acc[mt][nt], af[cur][mt], bf[cur][nt]);
        }
    }

    // epilogue
#pragma unroll
    for (int mt = 0; mt < 4; mt++) {
#pragma unroll
        for (int nt = 0; nt < 4; nt++) {
            int n = bn0 + wn + nt * 8 + 2 * tig;
            float b0 = biasp[n], b1 = biasp[n + 1];
#pragma unroll
            for (int half_i = 0; half_i < 2; half_i++) {
                int m = bm0 + wm + mt * 16 + gid + half_i * 8;
                float v0 = acc[mt][nt][half_i * 2]     + b0;
                float v1 = acc[mt][nt][half_i * 2 + 1] + b1;
                if (mode == 0) {
                    int part = n >> 8, cc = n & 255;
                    int head = cc >> 5, d = cc & 31;
                    int b = m >> 6, tok = m & 63;
                    if (part == 0) { v0 *= SCALE_Q; v1 *= SCALE_Q; }
                    __half* dst = (part == 0) ? g_qh : ((part == 1) ? g_kh : g_vh);
                    __half2 h = __floats2half2_rn(v0, v1);
                    *(__half2*)&dst[(((size_t)(b * NHEAD + head)) * NTOK + tok) * HD + d] = h;
                } else {
                    float2 r2; r2.x = v0; r2.y = v1;
                    *(float2*)&out[(size_t)m * CH + n] = r2;
                }
            }
        }
    }
}

// ---------------- tensor-core attention, fp16 ----------------
__global__ __launch_bounds__(128) void attn_kernel(
    const float* __restrict__ rel_table, const float* __restrict__ ego_table,
    const float* __restrict__ wvec)
{
    __shared__ __half sQK[2 * NTOK * 40];   // sq then sk (halfs); sP 64x72 overlays
    __shared__ __half svT[HD][72];          // V^T [d][m]
    __shared__ float  srel[225];

    __half* sq = sQK;
    __half* sk = sQK + NTOK * 40;

    int bh = blockIdx.x;
    int b = bh >> 3, head = bh & 7;
    int tid = threadIdx.x, warp = tid >> 5, lane = tid & 31;
    int gid = lane >> 2, tig = lane & 3;
    int wm = warp * 16;
    size_t base = (size_t)bh * (NTOK * HD);

    int n0 = wm + gid, n1 = wm + gid + 8;

    uint32_t sqB  = (uint32_t)__cvta_generic_to_shared(sq);
    uint32_t skB  = (uint32_t)__cvta_generic_to_shared(sk);
    uint32_t svTB = (uint32_t)__cvta_generic_to_shared(&svT[0][0]);
    uint32_t sPB  = sqB;   // overlay

    int aRow = lane & 15;
    int aCol = (lane >> 4) * 8;
    int bRow = ((lane >> 4) << 3) + (lane & 7);
    int bCol = ((lane >> 3) & 1) * 8;

    // tiles: 64 rows x 32 halfs = 256 uint4 groups (2 iterations of 128 threads)
#pragma unroll
    for (int i = 0; i < 2; i++) {
        int v = tid + i * 128;                 // 0..255
        int row = v >> 2, c8 = (v & 3) * 8;    // row 0..63, c8 in {0,8,16,24}
        *(uint4*)&sq[row * 40 + c8] = *(const uint4*)(g_qh + base + row * HD + c8);
        *(uint4*)&sk[row * 40 + c8] = *(const uint4*)(g_kh + base + row * HD + c8);
        uint4 vd = *(const uint4*)(g_vh + base + row * HD + c8);
        const __half* vh = (const __half*)&vd;
#pragma unroll
        for (int j = 0; j < 8; j++) svT[c8 + j][row] = vh[j];
    }
    for (int i = tid; i < 225; i += 128) srel[i] = rel_table[i * NHEAD + head];
    __syncthreads();

    // ---- S = q @ k^T : 2 k16 steps over d=32 ----
    float sacc[8][4];
#pragma unroll
    for (int nt = 0; nt < 8; nt++)
#pragma unroll
        for (int e = 0; e < 4; e++) sacc[nt][e] = 0.0f;

#pragma unroll
    for (int ksi = 0; ksi < 2; ksi++) {
        uint32_t qf[4], bf[8][2];
        ldsm4(qf[0], qf[1], qf[2], qf[3],
              sqB + ((wm + aRow) * 40 + ksi*16 + aCol) * 2);
#pragma unroll
        for (int p = 0; p < 4; p++)
            ldsm4(bf[2*p][0], bf[2*p][1], bf[2*p+1][0], bf[2*p+1][1],
                  skB + ((p*16 + bRow) * 40 + ksi*16 + bCol) * 2);
#pragma unroll
        for (int nt = 0; nt < 8; nt++) mma_f16(sacc[nt], qf, bf[nt]);
    }

    // biases
    float ego_b = ego_table[g_egoidx[b] * NHEAD + head];
    int ny0 = n0 >> 3, nx0 = n0 & 7, ny1 = n1 >> 3, nx1 = n1 & 7;
#pragma unroll
    for (int nt = 0; nt < 8; nt++) {
#pragma unroll
        for (int e = 0; e < 4; e++) {
            int m = nt * 8 + 2 * tig + (e & 1);
            int my = m >> 3, mx = m & 7;
            int ny = (e < 2) ? ny0 : ny1, nx = (e < 2) ? nx0 : nx1;
            sacc[nt][e] += srel[(ny - my + 7) * 15 + (nx - mx + 7)] + ego_b;
        }
    }

    // mixing weights
    float w0 = wvec[0], w1 = wvec[1];
    float mw = fmaxf(w0, w1);
    float e0w = __expf(w0 - mw), e1w = __expf(w1 - mw);
    float inv_w = 1.0f / (e0w + e1w);
    float ws0 = e0w * inv_w, ws1 = e1w * inv_w;

    // ---- register softmax over quad ----
    float mx0 = -1e30f, mx1 = -1e30f;
#pragma unroll
    for (int nt = 0; nt < 8; nt++) {
        mx0 = fmaxf(mx0, fmaxf(sacc[nt][0], sacc[nt][1]));
        mx1 = fmaxf(mx1, fmaxf(sacc[nt][2], sacc[nt][3]));
    }
    mx0 = fmaxf(mx0, __shfl_xor_sync(0xffffffffu, mx0, 1));
    mx0 = fmaxf(mx0, __shfl_xor_sync(0xffffffffu, mx0, 2));
    mx1 = fmaxf(mx1, __shfl_xor_sync(0xffffffffu, mx1, 1));
    mx1 = fmaxf(mx1, __shfl_xor_sync(0xffffffffu, mx1, 2));

    float sum0 = 0.0f, sum1 = 0.0f;
#pragma unroll
    for (int nt = 0; nt < 8; nt++) {
        sum0 += __expf(sacc[nt][0] - mx0);
        sum0 += __expf(sacc[nt][1] - mx0);
        sum1 += __expf(sacc[nt][2] - mx1);
        sum1 += __expf(sacc[nt][3] - mx1);
    }
    sum0 += __shfl_xor_sync(0xffffffffu, sum0, 1);
    sum0 += __shfl_xor_sync(0xffffffffu, sum0, 2);
    sum1 += __shfl_xor_sync(0xffffffffu, sum1, 1);
    sum1 += __shfl_xor_sync(0xffffffffu, sum1, 2);
    float inv0 = 1.0f / sum0, inv1 = 1.0f / sum1;

    __syncthreads();   // all warps done reading sq/sk -> safe to overlay sP

#pragma unroll
    for (int nt = 0; nt < 8; nt++) {
        float r0a = fmaxf(sacc[nt][0], 0.0f), r0b = fmaxf(sacc[nt][1], 0.0f);
        float r1a = fmaxf(sacc[nt][2], 0.0f), r1b = fmaxf(sacc[nt][3], 0.0f);
        __half2 P0 = __floats2half2_rn(ws0 * __expf(sacc[nt][0] - mx0) * inv0 + ws1 * r0a * r0a,
                                       ws0 * __expf(sacc[nt][1] - mx0) * inv0 + ws1 * r0b * r0b);
        __half2 P1 = __floats2half2_rn(ws0 * __expf(sacc[nt][2] - mx1) * inv1 + ws1 * r1a * r1a,
                                       ws0 * __expf(sacc[nt][3] - mx1) * inv1 + ws1 * r1b * r1b);
        *(__half2*)&sQK[n0 * 72 + nt * 8 + 2 * tig] = P0;
        *(__half2*)&sQK[n1 * 72 + nt * 8 + 2 * tig] = P1;
    }
    __syncwarp();      // each warp only reads its own sP rows below

    // ---- O = P @ V : 4 k16 steps over m=64 ----
    float oacc[4][4];
#pragma unroll
    for (int nt = 0; nt < 4; nt++)
#pragma unroll
        for (int e = 0; e < 4; e++) oacc[nt][e] = 0.0f;

#pragma unroll
    for (int ksi = 0; ksi < 4; ksi++) {
        uint32_t pf[4], vf[4][2];
        ldsm4(pf[0], pf[1], pf[2], pf[3],
              sPB + ((wm + aRow) * 72 + ksi*16 + aCol) * 2);
#pragma unroll
        for (int pp = 0; pp < 2; pp++)
            ldsm4(vf[2*pp][0], vf[2*pp][1], vf[2*pp+1][0], vf[2*pp+1][1],
                  svTB + ((pp*16 + bRow) * 72 + ksi*16 + bCol) * 2);
#pragma unroll
        for (int nt = 0; nt < 4; nt++) mma_f16(oacc[nt], pf, vf[nt]);
    }

    // store fp16: feeds the mode-1 GEMM
    __half* aop = g_aoh + (size_t)(b * NTOK) * CH + head * HD;
#pragma unroll
    for (int nt = 0; nt < 4; nt++) {
        int d0 = nt * 8 + 2 * tig;
        __half2 s0 = __floats2half2_rn(oacc[nt][0], oacc[nt][1]);
        __half2 s1 = __floats2half2_rn(oacc[nt][2], oacc[nt][3]);
        *(__half2*)(aop + (size_t)n0 * CH + d0) = s0;
        *(__half2*)(aop + (size_t)n1 * CH + d0) = s1;
    }
}

// ---------------- launch ----------------
extern "C" void kernel_launch(void* const* d_in, const int* in_sizes, int n_in,
                              void* d_out, int out_size) {
    const float* x    = (const float*)d_in[0];
    const float* aff  = (const float*)d_in[1];
    const float* Wq   = (const float*)d_in[2];
    const float* bq   = (const float*)d_in[3];
    const float* Wkv  = (const float*)d_in[4];
    const float* bkv  = (const float*)d_in[5];
    const float* Wp   = (const float*)d_in[6];
    const float* bp   = (const float*)d_in[7];
    const float* rel  = (const float*)d_in[8];
    const float* ego  = (const float*)d_in[9];
    const float* w    = (const float*)d_in[10];
    float* out = (float*)d_out;

    const int GEMM_SMEM = (128*264 + 2*128*40) * 2;   // 88064 B
    static int attr_set = 0;
    if (!attr_set) {
        cudaFuncSetAttribute(gemm_f16, cudaFuncAttributeMaxDynamicSharedMemorySize, GEMM_SMEM);
        attr_set = 1;
    }

    pack_kernel<<<768, 256>>>(Wq, bq, Wkv, bkv, Wp);
    ego_kernel<<<1, 256>>>(aff);
    prep_x<<<16384, 256>>>(x);
    gemm_f16<<<dim3(6, 1024), 256, GEMM_SMEM>>>(nullptr, 0, nullptr);
    attn_kernel<<<BWIN * NHEAD, 128>>>(rel, ego, w);
    gemm_f16<<<dim3(2, 1024), 256, GEMM_SMEM>>>(bp, 1, out);
}

// round 10
// speedup vs baseline: 1.5405x; 1.0398x over previous
#include <cuda_runtime.h>
#include <cuda_fp16.h>
#include <cstdint>
#include <cstddef>

// ---------------- problem constants ----------------
#define NCAV     2
#define WIN      8
#define BWIN     2048
#define NTOK     64
#define CH       256
#define NHEAD    8
#define HD       32
#define MROWS    (BWIN*NTOK)    // 131072
#define SCALE_Q  0.17677669529663687f
#define PI_F     3.14159274101257324f

// ---------------- scratch (fp16 pipeline) ----------------
__device__ __half g_xh  [(size_t)MROWS*CH];       // x, fp16
__device__ __half g_qh  [BWIN*NHEAD*NTOK*HD];
__device__ __half g_kh  [BWIN*NHEAD*NTOK*HD];
__device__ __half g_vh  [BWIN*NHEAD*NTOK*HD];
__device__ __half g_aoh [(size_t)MROWS*CH];       // attn output, fp16
__device__ __half g_wqkvh[768*CH];                // [n][k] transposed fp16
__device__ __half g_wph [CH*CH];                  // [n][k] transposed fp16
__device__ float  g_bqkv[768];
__device__ int    g_egoidx[BWIN];

// ---------------- helpers ----------------
__device__ __forceinline__ void mma_f16(float c[4], const uint32_t a[4], const uint32_t b[2]) {
    asm volatile(
        "mma.sync.aligned.m16n8k16.row.col.f32.f16.f16.f32 "
        "{%0,%1,%2,%3},{%4,%5,%6,%7},{%8,%9},{%0,%1,%2,%3};\n"
        : "+f"(c[0]), "+f"(c[1]), "+f"(c[2]), "+f"(c[3])
        : "r"(a[0]), "r"(a[1]), "r"(a[2]), "r"(a[3]), "r"(b[0]), "r"(b[1]));
}

__device__ __forceinline__ void ldsm4(uint32_t& r0, uint32_t& r1, uint32_t& r2, uint32_t& r3,
                                      uint32_t saddr) {
    asm volatile("ldmatrix.sync.aligned.m8n8.x4.shared.b16 {%0,%1,%2,%3}, [%4];\n"
                 : "=r"(r0), "=r"(r1), "=r"(r2), "=r"(r3) : "r"(saddr));
}

__device__ __forceinline__ void cpasync16(void* s, const void* g) {
    uint32_t sa = (uint32_t)__cvta_generic_to_shared(s);
    asm volatile("cp.async.cg.shared.global [%0], [%1], 16;\n" :: "r"(sa), "l"(g));
}

// ---------------- kernel 1: pack weights transposed [n][k] fp16 ----------------
__global__ void pack_kernel(const float* __restrict__ Wq, const float* __restrict__ bq,
                            const float* __restrict__ Wkv, const float* __restrict__ bkv,
                            const float* __restrict__ Wp) {
    int t = blockIdx.x * blockDim.x + threadIdx.x;  // 196608
    int n = t >> 8, k = t & 255;
    g_wqkvh[t] = __float2half_rn((n < CH) ? Wq[k*CH + n] : Wkv[k*512 + (n - CH)]);
    if (t < 768) g_bqkv[t] = (t < CH) ? bq[t] : bkv[t - CH];
    if (t < CH*CH) g_wph[t] = __float2half_rn(Wp[k*CH + n]);
}

// ---------------- kernel 2: x -> fp16 ----------------
__global__ void prep_x(const float* __restrict__ x) {
    size_t i = ((size_t)blockIdx.x * 256 + threadIdx.x) * 8;
    float4 a = *(const float4*)(x + i);
    float4 b = *(const float4*)(x + i + 4);
    __half2 h[4];
    h[0] = __floats2half2_rn(a.x, a.y);
    h[1] = __floats2half2_rn(a.z, a.w);
    h[2] = __floats2half2_rn(b.x, b.y);
    h[3] = __floats2half2_rn(b.z, b.w);
    *(uint4*)(g_xh + i) = *(uint4*)h;
}

// ---------------- kernel 3: ego bias bin index ----------------
__global__ void ego_kernel(const float* __restrict__ A) {
    __shared__ float rx[BWIN], ry[BWIN];
    __shared__ float red[256];
    int tid = threadIdx.x;
    float ex[NCAV], ey[NCAV];
#pragma unroll
    for (int c = 0; c < NCAV; c++) {
        ex[c] = A[c*6 + 0] * 128.0f + A[c*6 + 1] * 128.0f + A[c*6 + 2];
        ey[c] = A[c*6 + 3] * 128.0f + A[c*6 + 4] * 128.0f + A[c*6 + 5];
    }
    float lmax = 0.0f;
    for (int i = tid; i < BWIN; i += 256) {
        int cav = i >> 10, wi = i & 1023;
        int gy = wi >> 5, gx = wi & 31;
        float cx = gx * (float)WIN + WIN * 0.5f;
        float cy = gy * (float)WIN + WIN * 0.5f;
        float rxx = cx - ex[cav], ryy = cy - ey[cav];
        rx[i] = rxx; ry[i] = ryy;
        lmax = fmaxf(lmax, sqrtf(rxx*rxx + ryy*ryy));
    }
    red[tid] = lmax;
    __syncthreads();
    for (int s = 128; s > 0; s >>= 1) {
        if (tid < s) red[tid] = fmaxf(red[tid], red[tid + s]);
        __syncthreads();
    }
    float maxd = red[0] + 1e-6f;
    for (int i = tid; i < BWIN; i += 256) {
        float rxx = rx[i], ryy = ry[i];
        float d = sqrtf(rxx*rxx + ryy*ryy);
        int db = (int)(d / maxd * 3.0f);
        float ang = atan2f(ryy, rxx);
        int ab = (int)((ang + PI_F) / (2.0f * PI_F) * 3.0f);
        g_egoidx[i] = db * 4 + ab;
    }
}

// ---------------- GEMM fp16: resident B-tile + 3-stage streamed A ----------
// C[M,N] = A[M,256] @ B^T + bias, B [n][k] fp16.
// dyn smem (halfs): Bs[128][264] then As[3][128][40]   (98304 B)
#define BS_OFF(r, c)      ((r)*264 + (c))
#define AS_OFF(st, r, c)  (33792 + ((st)*128 + (r))*40 + (c))

#define ISSUE_A(st, kt) do {                                                  \
    _Pragma("unroll")                                                         \
    for (int ii = 0; ii < 2; ii++) {                                          \
        int c = tid + ii * 256;                                               \
        int row = c >> 2, kc = (c & 3) * 8;                                   \
        cpasync16(&hsm[AS_OFF(st, row, kc)],                                  \
                  Ap + (size_t)(bm0 + row) * 256 + (kt) * 32 + kc);           \
    }                                                                         \
    asm volatile("cp.async.commit_group;\n");                                 \
} while (0)

#define LOAD_FRAGS(buf, st, kglob, ks) do {                                   \
    _Pragma("unroll")                                                         \
    for (int mt = 0; mt < 4; mt++)                                            \
        ldsm4(af[buf][mt][0], af[buf][mt][1], af[buf][mt][2], af[buf][mt][3], \
              smemBase + AS_OFF(st, wm + mt*16 + aRow, (ks) + aCol) * 2);     \
    _Pragma("unroll")                                                         \
    for (int p = 0; p < 2; p++)                                               \
        ldsm4(bf[buf][2*p][0], bf[buf][2*p][1], bf[buf][2*p+1][0], bf[buf][2*p+1][1], \
              smemBase + BS_OFF(wn + p*16 + bRow, (kglob) + (ks) + bCol) * 2);\
} while (0)

__global__ __launch_bounds__(256, 2) void gemm_f16(
    const float* __restrict__ bias_ext, int mode, float* __restrict__ out)
{
    extern __shared__ __half hsm[];
    const __half* __restrict__ Ap    = (mode == 0) ? g_xh : g_aoh;
    const __half* __restrict__ Bp    = (mode == 0) ? g_wqkvh : g_wph;
    const float*  __restrict__ biasp = (mode == 0) ? g_bqkv : bias_ext;

    const int bm0 = blockIdx.y * 128;
    const int bn0 = blockIdx.x * 128;
    int tid = threadIdx.x, warp = tid >> 5, lane = tid & 31;
    int wm = (warp & 1) * 64, wn = (warp >> 1) * 32;
    int gid = lane >> 2, tig = lane & 3;

    uint32_t smemBase = (uint32_t)__cvta_generic_to_shared(hsm);
    int aRow = lane & 15;                         // A row within 16-tile
    int aCol = (lane >> 4) * 8;                   // A k-halfword group
    int bRow = ((lane >> 4) << 3) + (lane & 7);   // B n row
    int bCol = ((lane >> 3) & 1) * 8;             // B k-halfword group

    // prologue: resident B tile (group 0), then A stages 0 and 1
#pragma unroll
    for (int ii = 0; ii < 16; ii++) {
        int c = tid + ii * 256;
        int row = c >> 5, kc = (c & 31) * 8;
        cpasync16(&hsm[BS_OFF(row, kc)], Bp + (size_t)(bn0 + row) * 256 + kc);
    }
    asm volatile("cp.async.commit_group;\n");
    ISSUE_A(0, 0);
    ISSUE_A(1, 1);

    float acc[4][4][4];
#pragma unroll
    for (int i = 0; i < 4; i++)
#pragma unroll
        for (int j = 0; j < 4; j++)
#pragma unroll
            for (int e = 0; e < 4; e++) acc[i][j][e] = 0.0f;

#pragma unroll
    for (int kt = 0; kt < 8; kt++) {
        int st = kt % 3;
        if (kt < 7) { asm volatile("cp.async.wait_group 1;\n"); }   // A(kt) done, A(kt+1) may fly
        else        { asm volatile("cp.async.wait_group 0;\n"); }
        __syncthreads();                     // publishes stage kt; frees stage (kt+2)%3
        if (kt + 2 < 8) ISSUE_A((kt + 2) % 3, kt + 2);

        uint32_t af[2][4][4], bf[2][4][2];
        LOAD_FRAGS(0, st, kt * 32, 0);
#pragma unroll
        for (int ksq = 0; ksq < 2; ksq++) {       // two k16 steps per 32-k tile
            int cur = ksq & 1;
            if (ksq == 0) LOAD_FRAGS(1, st, kt * 32, 16);
#pragma unroll
            for (int mt = 0; mt < 4; mt++)
#pragma unroll
                for (int nt = 0; nt < 4; nt++)
                    mma_f16(acc[mt][nt], af[cur][mt], bf[cur][nt]);
        }
    }

    // epilogue
#pragma unroll
    for (int mt = 0; mt < 4; mt++) {
#pragma unroll
        for (int nt = 0; nt < 4; nt++) {
            int n = bn0 + wn + nt * 8 + 2 * tig;
            float b0 = biasp[n], b1 = biasp[n + 1];
#pragma unroll
            for (int half_i = 0; half_i < 2; half_i++) {
                int m = bm0 + wm + mt * 16 + gid + half_i * 8;
                float v0 = acc[mt][nt][half_i * 2]     + b0;
                float v1 = acc[mt][nt][half_i * 2 + 1] + b1;
                if (mode == 0) {
                    int part = n >> 8, cc = n & 255;
                    int head = cc >> 5, d = cc & 31;
                    int b = m >> 6, tok = m & 63;
                    if (part == 0) { v0 *= SCALE_Q; v1 *= SCALE_Q; }
                    __half* dst = (part == 0) ? g_qh : ((part == 1) ? g_kh : g_vh);
                    __half2 h = __floats2half2_rn(v0, v1);
                    *(__half2*)&dst[(((size_t)(b * NHEAD + head)) * NTOK + tok) * HD + d] = h;
                } else {
                    float2 r2; r2.x = v0; r2.y = v1;
                    *(float2*)&out[(size_t)m * CH + n] = r2;
                }
            }
        }
    }
}

// ---------------- tensor-core attention, fp16 ----------------
__global__ __launch_bounds__(128) void attn_kernel(
    const float* __restrict__ rel_table, const float* __restrict__ ego_table,
    const float* __restrict__ wvec)
{
    __shared__ __half sQK[2 * NTOK * 40];   // sq then sk (halfs); sP 64x72 overlays
    __shared__ __half svT[HD][72];          // V^T [d][m]
    __shared__ float  srel[225];

    __half* sq = sQK;
    __half* sk = sQK + NTOK * 40;

    int bh = blockIdx.x;
    int b = bh >> 3, head = bh & 7;
    int tid = threadIdx.x, warp = tid >> 5, lane = tid & 31;
    int gid = lane >> 2, tig = lane & 3;
    int wm = warp * 16;
    size_t base = (size_t)bh * (NTOK * HD);

    int n0 = wm + gid, n1 = wm + gid + 8;

    uint32_t sqB  = (uint32_t)__cvta_generic_to_shared(sq);
    uint32_t skB  = (uint32_t)__cvta_generic_to_shared(sk);
    uint32_t svTB = (uint32_t)__cvta_generic_to_shared(&svT[0][0]);
    uint32_t sPB  = sqB;   // overlay

    int aRow = lane & 15;
    int aCol = (lane >> 4) * 8;
    int bRow = ((lane >> 4) << 3) + (lane & 7);
    int bCol = ((lane >> 3) & 1) * 8;

    // tiles: 64 rows x 32 halfs = 256 uint4 groups (2 iterations of 128 threads)
#pragma unroll
    for (int i = 0; i < 2; i++) {
        int v = tid + i * 128;                 // 0..255
        int row = v >> 2, c8 = (v & 3) * 8;    // row 0..63, c8 in {0,8,16,24}
        *(uint4*)&sq[row * 40 + c8] = *(const uint4*)(g_qh + base + row * HD + c8);
        *(uint4*)&sk[row * 40 + c8] = *(const uint4*)(g_kh + base + row * HD + c8);
        uint4 vd = *(const uint4*)(g_vh + base + row * HD + c8);
        const __half* vh = (const __half*)&vd;
#pragma unroll
        for (int j = 0; j < 8; j++) svT[c8 + j][row] = vh[j];
    }
    for (int i = tid; i < 225; i += 128) srel[i] = rel_table[i * NHEAD + head];
    __syncthreads();

    // ---- S = q @ k^T : 2 k16 steps over d=32 ----
    float sacc[8][4];
#pragma unroll
    for (int nt = 0; nt < 8; nt++)
#pragma unroll
        for (int e = 0; e < 4; e++) sacc[nt][e] = 0.0f;

#pragma unroll
    for (int ksi = 0; ksi < 2; ksi++) {
        uint32_t qf[4], bf[8][2];
        ldsm4(qf[0], qf[1], qf[2], qf[3],
              sqB + ((wm + aRow) * 40 + ksi*16 + aCol) * 2);
#pragma unroll
        for (int p = 0; p < 4; p++)
            ldsm4(bf[2*p][0], bf[2*p][1], bf[2*p+1][0], bf[2*p+1][1],
                  skB + ((p*16 + bRow) * 40 + ksi*16 + bCol) * 2);
#pragma unroll
        for (int nt = 0; nt < 8; nt++) mma_f16(sacc[nt], qf, bf[nt]);
    }

    // biases
    float ego_b = ego_table[g_egoidx[b] * NHEAD + head];
    int ny0 = n0 >> 3, nx0 = n0 & 7, ny1 = n1 >> 3, nx1 = n1 & 7;
#pragma unroll
    for (int nt = 0; nt < 8; nt++) {
#pragma unroll
        for (int e = 0; e < 4; e++) {
            int m = nt * 8 + 2 * tig + (e & 1);
            int my = m >> 3, mx = m & 7;
            int ny = (e < 2) ? ny0 : ny1, nx = (e < 2) ? nx0 : nx1;
            sacc[nt][e] += srel[(ny - my + 7) * 15 + (nx - mx + 7)] + ego_b;
        }
    }

    // mixing weights
    float w0 = wvec[0], w1 = wvec[1];
    float mw = fmaxf(w0, w1);
    float e0w = __expf(w0 - mw), e1w = __expf(w1 - mw);
    float inv_w = 1.0f / (e0w + e1w);
    float ws0 = e0w * inv_w, ws1 = e1w * inv_w;

    // ---- register softmax over quad ----
    float mx0 = -1e30f, mx1 = -1e30f;
#pragma unroll
    for (int nt = 0; nt < 8; nt++) {
        mx0 = fmaxf(mx0, fmaxf(sacc[nt][0], sacc[nt][1]));
        mx1 = fmaxf(mx1, fmaxf(sacc[nt][2], sacc[nt][3]));
    }
    mx0 = fmaxf(mx0, __shfl_xor_sync(0xffffffffu, mx0, 1));
    mx0 = fmaxf(mx0, __shfl_xor_sync(0xffffffffu, mx0, 2));
    mx1 = fmaxf(mx1, __shfl_xor_sync(0xffffffffu, mx1, 1));
    mx1 = fmaxf(mx1, __shfl_xor_sync(0xffffffffu, mx1, 2));

    float sum0 = 0.0f, sum1 = 0.0f;
#pragma unroll
    for (int nt = 0; nt < 8; nt++) {
        sum0 += __expf(sacc[nt][0] - mx0);
        sum0 += __expf(sacc[nt][1] - mx0);
        sum1 += __expf(sacc[nt][2] - mx1);
        sum1 += __expf(sacc[nt][3] - mx1);
    }
    sum0 += __shfl_xor_sync(0xffffffffu, sum0, 1);
    sum0 += __shfl_xor_sync(0xffffffffu, sum0, 2);
    sum1 += __shfl_xor_sync(0xffffffffu, sum1, 1);
    sum1 += __shfl_xor_sync(0xffffffffu, sum1, 2);
    float inv0 = 1.0f / sum0, inv1 = 1.0f / sum1;

    __syncthreads();   // all warps done reading sq/sk -> safe to overlay sP

#pragma unroll
    for (int nt = 0; nt < 8; nt++) {
        float r0a = fmaxf(sacc[nt][0], 0.0f), r0b = fmaxf(sacc[nt][1], 0.0f);
        float r1a = fmaxf(sacc[nt][2], 0.0f), r1b = fmaxf(sacc[nt][3], 0.0f);
        __half2 P0 = __floats2half2_rn(ws0 * __expf(sacc[nt][0] - mx0) * inv0 + ws1 * r0a * r0a,
                                       ws0 * __expf(sacc[nt][1] - mx0) * inv0 + ws1 * r0b * r0b);
        __half2 P1 = __floats2half2_rn(ws0 * __expf(sacc[nt][2] - mx1) * inv1 + ws1 * r1a * r1a,
                                       ws0 * __expf(sacc[nt][3] - mx1) * inv1 + ws1 * r1b * r1b);
        *(__half2*)&sQK[n0 * 72 + nt * 8 + 2 * tig] = P0;
        *(__half2*)&sQK[n1 * 72 + nt * 8 + 2 * tig] = P1;
    }
    __syncwarp();      // each warp only reads its own sP rows below

    // ---- O = P @ V : 4 k16 steps over m=64 ----
    float oacc[4][4];
#pragma unroll
    for (int nt = 0; nt < 4; nt++)
#pragma unroll
        for (int e = 0; e < 4; e++) oacc[nt][e] = 0.0f;

#pragma unroll
    for (int ksi = 0; ksi < 4; ksi++) {
        uint32_t pf[4], vf[4][2];
        ldsm4(pf[0], pf[1], pf[2], pf[3],
              sPB + ((wm + aRow) * 72 + ksi*16 + aCol) * 2);
#pragma unroll
        for (int pp = 0; pp < 2; pp++)
            ldsm4(vf[2*pp][0], vf[2*pp][1], vf[2*pp+1][0], vf[2*pp+1][1],
                  svTB + ((pp*16 + bRow) * 72 + ksi*16 + bCol) * 2);
#pragma unroll
        for (int nt = 0; nt < 4; nt++) mma_f16(oacc[nt], pf, vf[nt]);
    }

    // store fp16: feeds the mode-1 GEMM
    __half* aop = g_aoh + (size_t)(b * NTOK) * CH + head * HD;
#pragma unroll
    for (int nt = 0; nt < 4; nt++) {
        int d0 = nt * 8 + 2 * tig;
        __half2 s0 = __floats2half2_rn(oacc[nt][0], oacc[nt][1]);
        __half2 s1 = __floats2half2_rn(oacc[nt][2], oacc[nt][3]);
        *(__half2*)(aop + (size_t)n0 * CH + d0) = s0;
        *(__half2*)(aop + (size_t)n1 * CH + d0) = s1;
    }
}

// ---------------- launch ----------------
extern "C" void kernel_launch(void* const* d_in, const int* in_sizes, int n_in,
                              void* d_out, int out_size) {
    const float* x    = (const float*)d_in[0];
    const float* aff  = (const float*)d_in[1];
    const float* Wq   = (const float*)d_in[2];
    const float* bq   = (const float*)d_in[3];
    const float* Wkv  = (const float*)d_in[4];
    const float* bkv  = (const float*)d_in[5];
    const float* Wp   = (const float*)d_in[6];
    const float* bp   = (const float*)d_in[7];
    const float* rel  = (const float*)d_in[8];
    const float* ego  = (const float*)d_in[9];
    const float* w    = (const float*)d_in[10];
    float* out = (float*)d_out;

    const int GEMM_SMEM = (128*264 + 3*128*40) * 2;   // 98304 B -> 2 CTAs/SM
    static int attr_set = 0;
    if (!attr_set) {
        cudaFuncSetAttribute(gemm_f16, cudaFuncAttributeMaxDynamicSharedMemorySize, GEMM_SMEM);
        attr_set = 1;
    }

    pack_kernel<<<768, 256>>>(Wq, bq, Wkv, bkv, Wp);
    ego_kernel<<<1, 256>>>(aff);
    prep_x<<<16384, 256>>>(x);
    gemm_f16<<<dim3(6, 1024), 256, GEMM_SMEM>>>(nullptr, 0, nullptr);
    attn_kernel<<<BWIN * NHEAD, 128>>>(rel, ego, w);
    gemm_f16<<<dim3(2, 1024), 256, GEMM_SMEM>>>(bp, 1, out);
}